// round 3
// baseline (speedup 1.0000x reference)
#include <cuda_runtime.h>
#include <cuda_bf16.h>

// DifferentiableHMM_Centered — GB300 sm_103a, R3
//
// Math reduction (R1): straight-through gumbel-softmax argmax collapses to
//   norm_copy[s,j] = all_means[argmax_k(log_em_k + gumbel_k)]
//   smooth_loss    = 0.1 * 2 * (#(state[row] != state[col]) over edges×bins) / (E*Bc*3)
//
// R3: edge_kernel restructured for MLP — rows padded to 48 uint4 (768 B), each
// lane issues up to 4 independent 16B L2 loads with no loop (was: 3-iteration
// runtime loop of 8B loads, issue-starved at 22.9%).

#define HALF_LOG_2PI 0.9189385332046727f

// 2048 rows x 128 u64 (1 KB/row capacity; 768 B used). Zero-initialized at
// module load; padding bytes are never written -> XOR contributes 0.
__device__ unsigned long long g_state[2048 * 128];
__device__ unsigned int g_count;
__device__ unsigned int g_done;

__device__ __forceinline__ void classify(float xv, float g0, float g1, float g2,
                                         const float* __restrict__ p,
                                         int& k, float& nv) {
    float z0 = (xv - p[0]) * p[2];
    float z1 = xv * p[3];              // middle state mean == 0
    float z2 = (xv - p[1]) * p[4];
    float l0 = fmaf(-0.5f * z0, z0, p[5]) + g0;
    float l1 = fmaf(-0.5f * z1, z1, p[6]) + g1;
    float l2 = fmaf(-0.5f * z2, z2, p[7]) + g2;
    k = 0; float best = l0; nv = p[0];
    if (l1 > best) { best = l1; k = 1; nv = 0.0f; }
    if (l2 > best) {            k = 2; nv = p[1]; }
}

__global__ void state_kernel(const float* __restrict__ x,
                             const int*   __restrict__ bin_idx,
                             const float* __restrict__ gumbel,
                             const float* __restrict__ state_means,
                             const float* __restrict__ log_stds,
                             float*       __restrict__ out,
                             int B, int Bc, int stride_bytes) {
    __shared__ float p[8];
    if (threadIdx.x == 0) {
        float s0 = expf(log_stds[0]) + 1e-6f;
        float s1 = expf(log_stds[1]) + 1e-6f;
        float s2 = expf(log_stds[2]) + 1e-6f;
        p[0] = state_means[0];
        p[1] = state_means[1];
        p[2] = 1.0f / s0;  p[3] = 1.0f / s1;  p[4] = 1.0f / s2;
        p[5] = -logf(s0) - HALF_LOG_2PI;
        p[6] = -logf(s1) - HALF_LOG_2PI;
        p[7] = -logf(s2) - HALF_LOG_2PI;
        if (blockIdx.x == 0 && blockIdx.y == 0) { g_count = 0u; g_done = 0u; }
    }
    __syncthreads();

    int groups = (Bc + 3) >> 2;
    int jt = blockIdx.x * blockDim.x + threadIdx.x;
    if (jt >= groups) return;
    int s  = blockIdx.y;
    int j0 = jt << 2;

    unsigned int pack = 0;
    float nv0 = 0.f, nv1 = 0.f, nv2 = 0.f, nv3 = 0.f;
    bool full = (j0 + 3 < Bc);
    bool fast = false;
    int src0 = __ldg(bin_idx + j0);
    size_t base = (size_t)s * (size_t)B + (size_t)src0;

    if (full) {
        int src1 = __ldg(bin_idx + j0 + 1);
        int src2 = __ldg(bin_idx + j0 + 2);
        int src3 = __ldg(bin_idx + j0 + 3);
        fast = (src1 == src0 + 1) && (src2 == src0 + 2) && (src3 == src0 + 3) &&
               ((base & 3) == 0);
        if (fast) {
            float4 xv = __ldg((const float4*)(x + base));
            const float4* g4 = (const float4*)(gumbel + base * 3u);
            float4 ga = __ldg(g4), gb = __ldg(g4 + 1), gc = __ldg(g4 + 2);
            int k;
            classify(xv.x, ga.x, ga.y, ga.z, p, k, nv0); pack  = (unsigned)k;
            classify(xv.y, ga.w, gb.x, gb.y, p, k, nv1); pack |= (unsigned)k << 2;
            classify(xv.z, gb.z, gb.w, gc.x, p, k, nv2); pack |= (unsigned)k << 4;
            classify(xv.w, gc.y, gc.z, gc.w, p, k, nv3); pack |= (unsigned)k << 6;
        }
    }
    if (!fast) {
        float nv[4] = {0.f, 0.f, 0.f, 0.f};
        for (int u = 0; u < 4; ++u) {
            int j = j0 + u;
            if (j >= Bc) break;
            int src = __ldg(bin_idx + j);
            size_t xi = (size_t)s * (size_t)B + (size_t)src;
            float xv = __ldg(x + xi);
            const float* g = gumbel + xi * 3u;
            int k;
            classify(xv, __ldg(g), __ldg(g + 1), __ldg(g + 2), p, k, nv[u]);
            pack |= (unsigned)k << (2 * u);
        }
        nv0 = nv[0]; nv1 = nv[1]; nv2 = nv[2]; nv3 = nv[3];
    }

    size_t oi = (size_t)s * (size_t)Bc + (size_t)j0;
    if (full && ((oi & 3) == 0)) {
        *(float4*)(out + oi) = make_float4(nv0, nv1, nv2, nv3);
    } else {
        if (j0 + 0 < Bc) out[oi + 0] = nv0;
        if (j0 + 1 < Bc) out[oi + 1] = nv1;
        if (j0 + 2 < Bc) out[oi + 2] = nv2;
        if (j0 + 3 < Bc) out[oi + 3] = nv3;
    }
    ((unsigned char*)g_state)[(size_t)s * (size_t)stride_bytes + (size_t)jt] =
        (unsigned char)pack;
}

__device__ __forceinline__ unsigned int mismatch16(uint4 a, uint4 b) {
    unsigned long long d0 = ((unsigned long long)(a.y ^ b.y) << 32) | (a.x ^ b.x);
    unsigned long long d1 = ((unsigned long long)(a.w ^ b.w) << 32) | (a.z ^ b.z);
    d0 = (d0 | (d0 >> 1)) & 0x5555555555555555ull;
    d1 = (d1 | (d1 >> 1)) & 0x5555555555555555ull;
    return (unsigned int)(__popcll(d0) + __popcll(d1));
}

__global__ void edge_kernel(const int* __restrict__ edge_index,
                            int E, int stride_u4,
                            float* __restrict__ loss_out, long long denom) {
    int warp = threadIdx.x >> 5;
    int lane = threadIdx.x & 31;
    int e = blockIdx.x * (blockDim.x >> 5) + warp;

    unsigned int cnt = 0;
    if (e < E) {
        int r = __ldg(edge_index + e);
        int c = __ldg(edge_index + E + e);
        if (r != c) {
            const uint4* a = (const uint4*)g_state + (size_t)r * (size_t)stride_u4;
            const uint4* b = (const uint4*)g_state + (size_t)c * (size_t)stride_u4;
            if (stride_u4 <= 64) {
                // all loads independent, issued before any compute
                bool p0 = lane < stride_u4;
                bool p1 = lane + 32 < stride_u4;
                uint4 va0 = make_uint4(0,0,0,0), vb0 = va0;
                uint4 va1 = va0, vb1 = va0;
                if (p0) { va0 = __ldg(a + lane);      vb0 = __ldg(b + lane); }
                if (p1) { va1 = __ldg(a + lane + 32); vb1 = __ldg(b + lane + 32); }
                if (p0) cnt += mismatch16(va0, vb0);
                if (p1) cnt += mismatch16(va1, vb1);
            } else {
                for (int w = lane; w < stride_u4; w += 32)
                    cnt += mismatch16(__ldg(a + w), __ldg(b + w));
            }
        }
    }
    cnt = __reduce_add_sync(0xffffffffu, cnt);

    __shared__ unsigned int sred[32];
    if (lane == 0) sred[warp] = cnt;
    __syncthreads();
    if (threadIdx.x == 0) {
        unsigned int tot = 0;
        int nw = blockDim.x >> 5;
        for (int i = 0; i < nw; ++i) tot += sred[i];
        if (tot) atomicAdd(&g_count, tot);
        __threadfence();
        unsigned int ticket = atomicAdd(&g_done, 1u);
        if (ticket == gridDim.x - 1) {
            unsigned int total = atomicAdd(&g_count, 0u);  // ordered read
            loss_out[0] = (float)(0.2 * (double)total / (double)denom);
            g_done = 0u;  // reset for next graph replay
        }
    }
}

extern "C" void kernel_launch(void* const* d_in, const int* in_sizes, int n_in,
                              void* d_out, int out_size) {
    const float* x           = (const float*)d_in[0];
    const int*   bin_idx     = (const int*)  d_in[1];
    const int*   edge_index  = (const int*)  d_in[2];
    const float* gumbel      = (const float*)d_in[3];
    const float* state_means = (const float*)d_in[4];
    const float* log_stds    = (const float*)d_in[5];
    float* out = (float*)d_out;

    int Bc = in_sizes[1];          // covered bins (output columns)
    int E  = in_sizes[2] / 2;      // edges
    int B  = Bc;                   // ranges cover all bins => B == Bc
    int S  = in_sizes[0] / B;      // spots

    int groups       = (Bc + 3) / 4;                  // state bytes per row
    int words        = (groups + 7) / 8;              // u64 words used
    int stride_words = (words + 15) & ~15;            // pad to uint4*16 = 128B
    if (stride_words > 128) stride_words = 128;       // capacity guard
    int stride_bytes = stride_words * 8;
    int stride_u4    = stride_words / 2;

    dim3 gridA((groups + 255) / 256, S);
    state_kernel<<<gridA, 256>>>(x, bin_idx, gumbel, state_means, log_stds,
                                 out, B, Bc, stride_bytes);

    const int WARPS_PER_BLOCK = 16;
    int gridB = (E + WARPS_PER_BLOCK - 1) / WARPS_PER_BLOCK;
    long long denom = (long long)E * (long long)Bc * 3ll;
    edge_kernel<<<gridB, WARPS_PER_BLOCK * 32>>>(
        edge_index, E, stride_u4, out + ((size_t)out_size - 1), denom);
}